// round 2
// baseline (speedup 1.0000x reference)
#include <cuda_runtime.h>
#include <cuda_fp16.h>

// Problem constants
#define T_STEPS   200
#define CH        64     // channels (LSTM input size)
#define HID       128    // hidden size
#define GATES     512    // 4*HID gate rows
#define KTOT      192    // CH + HID fused K dimension
#define TN        4      // sequences per block
#define NSEQ      480    // 16*30
#define NBLOCK    120    // NSEQ / TN
#define NTHREADS  256
#define WROW      194    // fp16 elements per weight row (192 + 2 pad) -> 388B, 97 banks: conflict-free

// SMEM layout (dynamic):
//  [0, 198656)            : fp16 weights, 512 rows x 194 halves
//  [198656, 206848)       : gates, 512 x float4 (one float4 = 4 sequences)
//  [206848, 212992)       : xh double buffer, 2 x 192 x float4
#define SM_W_BYTES   (GATES * WROW * 2)
#define SM_G_BYTES   (GATES * 16)
#define SM_XH_BYTES  (2 * KTOT * 16)
#define SMEM_BYTES   (SM_W_BYTES + SM_G_BYTES + SM_XH_BYTES)

// transposed x scratch: [seq][t][c], 480*200*64 floats = 24.6 MB
__device__ float g_xT[NSEQ * T_STEPS * CH];

// ---------------------------------------------------------------------------
// Kernel 1: transpose x (B, C, T, P) -> xT (B*P, T, C), coalesced both sides
// via a padded SMEM tile. One block per (b, t).
// ---------------------------------------------------------------------------
__global__ void transpose_kernel(const float* __restrict__ x) {
    const int b = blockIdx.x;   // 0..15
    const int t = blockIdx.y;   // 0..199
    __shared__ float s[30 * 65];

    const float* xb = x + (size_t)b * (CH * T_STEPS * 30) + (size_t)t * 30;
    for (int i = threadIdx.x; i < CH * 30; i += blockDim.x) {
        int c = i / 30, p = i - c * 30;
        s[p * 65 + c] = xb[(size_t)c * (T_STEPS * 30) + p];
    }
    __syncthreads();
    float* outp = g_xT + ((size_t)b * 30) * (T_STEPS * CH) + (size_t)t * CH;
    for (int i = threadIdx.x; i < 30 * CH; i += blockDim.x) {
        int p = i >> 6, c = i & 63;
        outp[(size_t)p * (T_STEPS * CH) + c] = s[p * 65 + c];
    }
}

// ---------------------------------------------------------------------------
// Fast accurate activations (MUFU.EX2 + MUFU.RCP based, ~1e-7 rel err)
// ---------------------------------------------------------------------------
__device__ __forceinline__ float sigm_f(float x) {
    return __fdividef(1.0f, 1.0f + __expf(-x));
}
__device__ __forceinline__ float tanh_f(float x) {
    float ax = fabsf(x);
    float e  = __expf(-2.0f * ax);
    float r  = (1.0f - e) * __fdividef(1.0f, 1.0f + e);
    return copysignf(r, x);
}
__device__ __forceinline__ void lstm_cell(float gi, float gf, float gg, float go,
                                          float& c, float& h) {
    float i_ = sigm_f(gi);
    float f_ = sigm_f(gf);
    float g_ = tanh_f(gg);
    float o_ = sigm_f(go);
    c = fmaf(f_, c, i_ * g_);
    h = o_ * tanh_f(c);
}

// ---------------------------------------------------------------------------
// Kernel 2: persistent LSTM. 120 blocks x 256 threads, 4 sequences per block.
// Thread tid computes gate rows r0 = tid (i/f rows) and r1 = tid+256 (g/o rows)
// for all 4 sequences. Weights stationary as fp16 in SMEM; activations in a
// float4-packed (over sequences) double buffer; fp32 accumulation.
// ---------------------------------------------------------------------------
__global__ void __launch_bounds__(NTHREADS, 1)
lstm_kernel(const float* __restrict__ W_ih, const float* __restrict__ W_hh,
            const float* __restrict__ b_ih, const float* __restrict__ b_hh,
            const float* __restrict__ W_fc, const float* __restrict__ b_fc,
            float* __restrict__ out) {
    extern __shared__ char smem[];
    __half*  ws     = (__half*)smem;                              // [512][194]
    float4*  gates4 = (float4*)(smem + SM_W_BYTES);               // [512]
    float4*  xh     = (float4*)(smem + SM_W_BYTES + SM_G_BYTES);  // [2][192]

    const int tid  = threadIdx.x;
    const int seq0 = blockIdx.x * TN;

    // ---- load weights -> fp16 SMEM (one-time) ----
    for (int idx = tid; idx < GATES * KTOT; idx += NTHREADS) {
        int r = idx / KTOT, k = idx - r * KTOT;
        float w = (k < CH) ? W_ih[r * CH + k] : W_hh[r * HID + (k - CH)];
        ws[r * WROW + k] = __float2half_rn(w);
    }

    const int r0 = tid;
    const int r1 = tid + 256;
    const float bias0 = b_ih[r0] + b_hh[r0];
    const float bias1 = b_ih[r1] + b_hh[r1];

    // ---- init xh[0]: x at t=0, h = 0 ----
    {
        int n = tid >> 6, c = tid & 63;
        float xv = g_xT[(size_t)(seq0 + n) * (T_STEPS * CH) + c];
        ((float*)&xh[c])[n] = xv;
        if (tid < HID) xh[CH + tid] = make_float4(0.f, 0.f, 0.f, 0.f);
    }
    float4 cst = make_float4(0.f, 0.f, 0.f, 0.f);  // cell state (tid < 128)
    __syncthreads();

    const __half2* w2  = (const __half2*)ws;          // [r][q], row stride 97
    const __half2* wr0 = w2 + r0 * (WROW / 2);
    const __half2* wr1 = w2 + r1 * (WROW / 2);

    for (int t = 0; t < T_STEPS; t++) {
        const int cb = t & 1, nb = cb ^ 1;
        const float4* v = xh + cb * KTOT;

        // prefetch x for t+1 (latency hidden behind the gate GEMV)
        const int n = tid >> 6, c = tid & 63;
        float xv = 0.f;
        if (t + 1 < T_STEPS)
            xv = g_xT[(size_t)(seq0 + n) * (T_STEPS * CH) + (t + 1) * CH + c];

        float4 a0 = make_float4(bias0, bias0, bias0, bias0);
        float4 a1 = make_float4(bias1, bias1, bias1, bias1);

        #pragma unroll 8
        for (int q = 0; q < KTOT / 2; q++) {
            float4 v0 = v[2 * q];        // broadcast LDS.128
            float4 v1 = v[2 * q + 1];    // broadcast LDS.128
            float2 f0 = __half22float2(wr0[q]);   // conflict-free LDS.32
            float2 f1 = __half22float2(wr1[q]);
            a0.x = fmaf(f0.x, v0.x, a0.x);
            a0.y = fmaf(f0.x, v0.y, a0.y);
            a0.z = fmaf(f0.x, v0.z, a0.z);
            a0.w = fmaf(f0.x, v0.w, a0.w);
            a0.x = fmaf(f0.y, v1.x, a0.x);
            a0.y = fmaf(f0.y, v1.y, a0.y);
            a0.z = fmaf(f0.y, v1.z, a0.z);
            a0.w = fmaf(f0.y, v1.w, a0.w);
            a1.x = fmaf(f1.x, v0.x, a1.x);
            a1.y = fmaf(f1.x, v0.y, a1.y);
            a1.z = fmaf(f1.x, v0.z, a1.z);
            a1.w = fmaf(f1.x, v0.w, a1.w);
            a1.x = fmaf(f1.y, v1.x, a1.x);
            a1.y = fmaf(f1.y, v1.y, a1.y);
            a1.z = fmaf(f1.y, v1.z, a1.z);
            a1.w = fmaf(f1.y, v1.w, a1.w);
        }
        gates4[r0] = a0;
        gates4[r1] = a1;
        __syncthreads();

        // epilogue: unit j = tid owns i=row j, f=row 128+j, g=row 256+j, o=row 384+j
        if (tid < HID) {
            float4 gi = gates4[tid];
            float4 gf = gates4[HID + tid];
            float4 gg = gates4[2 * HID + tid];
            float4 go = gates4[3 * HID + tid];
            float4 hv;
            lstm_cell(gi.x, gf.x, gg.x, go.x, cst.x, hv.x);
            lstm_cell(gi.y, gf.y, gg.y, go.y, cst.y, hv.y);
            lstm_cell(gi.z, gf.z, gg.z, go.z, cst.z, hv.z);
            lstm_cell(gi.w, gf.w, gg.w, go.w, cst.w, hv.w);
            xh[nb * KTOT + CH + tid] = hv;
        }
        if (t + 1 < T_STEPS)
            ((float*)&xh[nb * KTOT + c])[n] = xv;
        __syncthreads();
    }

    // final h lives in buffer 0 (T even). Compact to hb[n][j] (reuse gates SMEM).
    float* hb = (float*)gates4;  // [4][128]
    if (tid < HID) {
        float4 hv = xh[CH + tid];
        hb[0 * HID + tid] = hv.x;
        hb[1 * HID + tid] = hv.y;
        hb[2 * HID + tid] = hv.z;
        hb[3 * HID + tid] = hv.w;
    }
    __syncthreads();

    // tiny FC: out[seq][ch] = h . W_fc[ch] + b_fc[ch]
    {
        const int n = tid >> 6, chn = tid & 63;
        const float4* wfc4 = (const float4*)(W_fc + chn * HID);
        const float4* hb4  = (const float4*)(hb + n * HID);
        float acc = b_fc[chn];
        #pragma unroll
        for (int j4 = 0; j4 < HID / 4; j4++) {
            float4 wv = wfc4[j4];
            float4 hv = hb4[j4];
            acc = fmaf(wv.x, hv.x, acc);
            acc = fmaf(wv.y, hv.y, acc);
            acc = fmaf(wv.z, hv.z, acc);
            acc = fmaf(wv.w, hv.w, acc);
        }
        out[(size_t)(seq0 + n) * CH + chn] = acc;
    }
}

// ---------------------------------------------------------------------------
extern "C" void kernel_launch(void* const* d_in, const int* in_sizes, int n_in,
                              void* d_out, int out_size) {
    const float* x    = (const float*)d_in[0];
    const float* W_ih = (const float*)d_in[1];
    const float* W_hh = (const float*)d_in[2];
    const float* b_ih = (const float*)d_in[3];
    const float* b_hh = (const float*)d_in[4];
    const float* W_fc = (const float*)d_in[5];
    const float* b_fc = (const float*)d_in[6];
    float* out = (float*)d_out;

    cudaFuncSetAttribute(lstm_kernel,
                         cudaFuncAttributeMaxDynamicSharedMemorySize, SMEM_BYTES);

    transpose_kernel<<<dim3(16, T_STEPS), 256>>>(x);
    lstm_kernel<<<NBLOCK, NTHREADS, SMEM_BYTES>>>(W_ih, W_hh, b_ih, b_hh,
                                                  W_fc, b_fc, out);
}

// round 8
// speedup vs baseline: 3.6446x; 3.6446x over previous
#include <cuda_runtime.h>
#include <cuda_fp16.h>
#include <cstdint>

// Problem constants
#define T_STEPS   200
#define CH        64     // channels (LSTM input size)
#define HID       128    // hidden size
#define GATES     512    // 4*HID gate rows
#define KTOT      192    // CH + HID fused K
#define TN        4      // sequences per block
#define NSEQ      480    // 16*30
#define NBLOCK    120
#define NTHREADS  256
#define NKT       12     // K tiles of 16

// fp16 transposed x scratch: [seq][t][c]
__device__ __half g_xT[(size_t)NSEQ * T_STEPS * CH];

// ---------------------------------------------------------------------------
// Kernel 1: transpose x (B, C, T, P) -> g_xT (B*P, T, C) fp16
// ---------------------------------------------------------------------------
__global__ void transpose_kernel(const float* __restrict__ x) {
    const int b = blockIdx.x;   // 0..15
    const int t = blockIdx.y;   // 0..199
    __shared__ float s[30 * 65];

    const float* xb = x + (size_t)b * (CH * T_STEPS * 30) + (size_t)t * 30;
    for (int i = threadIdx.x; i < CH * 30; i += blockDim.x) {
        int c = i / 30, p = i - c * 30;
        s[p * 65 + c] = xb[(size_t)c * (T_STEPS * 30) + p];
    }
    __syncthreads();
    __half* outp = g_xT + ((size_t)b * 30) * (T_STEPS * CH) + (size_t)t * CH;
    for (int i = threadIdx.x; i < 30 * CH; i += blockDim.x) {
        int p = i >> 6, c = i & 63;
        outp[(size_t)p * (T_STEPS * CH) + c] = __float2half_rn(s[p * 65 + c]);
    }
}

// ---------------------------------------------------------------------------
// Accurate activations (EX2 + RCP MUFU based, ~1e-7 rel err)
// ---------------------------------------------------------------------------
__device__ __forceinline__ float sigm_f(float x) {
    return __fdividef(1.0f, 1.0f + __expf(-x));
}
__device__ __forceinline__ float tanh_f(float x) {
    float ax = fabsf(x);
    float e  = __expf(-2.0f * ax);
    float r  = (1.0f - e) * __fdividef(1.0f, 1.0f + e);
    return copysignf(r, x);
}
__device__ __forceinline__ void lstm_cell(float gi, float gf, float gg, float go,
                                          float& c, float& h) {
    float i_ = sigm_f(gi);
    float f_ = sigm_f(gf);
    float g_ = tanh_f(gg);
    float o_ = sigm_f(go);
    c = fmaf(f_, c, i_ * g_);
    h = o_ * tanh_f(c);
}

// ---------------------------------------------------------------------------
// m16n8k16 f16 -> f32 mma (baseline PTX, runs on sm_103 fallback HMMA)
// D = A*B + C
// ---------------------------------------------------------------------------
__device__ __forceinline__ void mma16816(float* d, const uint32_t* a,
                                         uint32_t b0, uint32_t b1,
                                         const float* c) {
    asm volatile(
        "mma.sync.aligned.m16n8k16.row.col.f32.f16.f16.f32 "
        "{%0,%1,%2,%3}, {%4,%5,%6,%7}, {%8,%9}, {%10,%11,%12,%13};"
        : "=f"(d[0]), "=f"(d[1]), "=f"(d[2]), "=f"(d[3])
        : "r"(a[0]), "r"(a[1]), "r"(a[2]), "r"(a[3]),
          "r"(b0), "r"(b1),
          "f"(c[0]), "f"(c[1]), "f"(c[2]), "f"(c[3]));
}

__device__ __forceinline__ float getW(const float* __restrict__ Wih,
                                      const float* __restrict__ Whh,
                                      int r, int k) {
    return (k < CH) ? Wih[r * CH + k] : Whh[r * HID + (k - CH)];
}
__device__ __forceinline__ uint32_t packw(const float* __restrict__ Wih,
                                          const float* __restrict__ Whh,
                                          int r, int k) {
    __half2 h = __floats2half2_rn(getW(Wih, Whh, r, k), getW(Wih, Whh, r, k + 1));
    return *(uint32_t*)&h;
}

// ---------------------------------------------------------------------------
// Kernel 2: persistent HMMA LSTM. 120 blocks x 256 threads, 4 seqs/block.
// Weights live as m16n8k16 A-fragments in registers (192 regs/thread).
// Per step: 8 warps x 4 m-tiles x 12 k-tiles of mma.sync; bias via C operand.
// B operand (x|h fp16) double-buffered in SMEM, scalar-LDS'd into b-frags.
// x-part (kt 0-3) of step t+1 overlaps the t epilogue's MUFU chain.
// ---------------------------------------------------------------------------
__global__ void __launch_bounds__(NTHREADS, 1)
lstm_kernel(const float* __restrict__ W_ih, const float* __restrict__ W_hh,
            const float* __restrict__ b_ih, const float* __restrict__ b_hh,
            const float* __restrict__ W_fc, const float* __restrict__ b_fc,
            float* __restrict__ out) {
    // av[buf][k2][n]: half2 = activations {val[2k2], val[2k2+1]} for seq-col n
    __shared__ __align__(16) __half2 av[2][96][8];      // 6 KB
    __shared__ __align__(16) float gates[GATES][4];     // 8 KB
    __shared__ float sbias[GATES];                      // 2 KB

    const int tid  = threadIdx.x;
    const int lane = tid & 31;
    const int wid  = tid >> 5;
    const int lg   = lane >> 2;   // group id (row / n-col)
    const int lq   = lane & 3;    // thread in group (k pairs / n pairs)
    const int seq0 = blockIdx.x * TN;

    // ---- preload weight A-fragments into registers (one-time) ----
    uint32_t Af[4][NKT][4];
    #pragma unroll
    for (int mi = 0; mi < 4; mi++) {
        const int mt  = wid * 4 + mi;
        const int rlo = mt * 16 + lg;
        const int rhi = rlo + 8;
        #pragma unroll
        for (int kt = 0; kt < NKT; kt++) {
            const int kb = kt * 16 + lq * 2;
            Af[mi][kt][0] = packw(W_ih, W_hh, rlo, kb);
            Af[mi][kt][1] = packw(W_ih, W_hh, rhi, kb);
            Af[mi][kt][2] = packw(W_ih, W_hh, rlo, kb + 8);
            Af[mi][kt][3] = packw(W_ih, W_hh, rhi, kb + 8);
        }
    }

    // ---- bias to SMEM, zero av buffers ----
    for (int r = tid; r < GATES; r += NTHREADS) sbias[r] = b_ih[r] + b_hh[r];
    for (int i = tid; i < 2 * 96 * 8; i += NTHREADS) ((uint32_t*)av)[i] = 0u;
    __syncthreads();

    // ---- x(t=0) into av[0] ----
    const int xn = tid >> 6, xk = tid & 63;
    ((__half*)&av[0][xk >> 1][xn])[xk & 1] =
        g_xT[((size_t)(seq0 + xn) * T_STEPS + 0) * CH + xk];
    __syncthreads();

    // per-lane bias (loaded from SMEM, cheap, saves registers)
    float acc[4][4];

    // ---- x-part for t = 0 (kt 0..3), C = bias ----
    {
        #pragma unroll
        for (int kt = 0; kt < 4; kt++) {
            uint32_t b0 = *(const uint32_t*)&av[0][kt * 8 + lq][lg];
            uint32_t b1 = *(const uint32_t*)&av[0][kt * 8 + 4 + lq][lg];
            #pragma unroll
            for (int mi = 0; mi < 4; mi++) {
                if (kt == 0) {
                    const int rlo = (wid * 4 + mi) * 16 + lg;
                    float blo = sbias[rlo], bhi = sbias[rlo + 8];
                    float cb[4] = {blo, blo, bhi, bhi};
                    mma16816(acc[mi], Af[mi][0], b0, b1, cb);
                } else {
                    mma16816(acc[mi], Af[mi][kt], b0, b1, acc[mi]);
                }
            }
        }
    }

    float cs[TN] = {0.f, 0.f, 0.f, 0.f};
    float hs[TN] = {0.f, 0.f, 0.f, 0.f};

    for (int t = 0; t < T_STEPS; t++) {
        const int cur = t & 1, nxt = cur ^ 1;

        // ---- h-part: kt 4..11 on av[cur] ----
        #pragma unroll
        for (int kt = 4; kt < NKT; kt++) {
            uint32_t b0 = *(const uint32_t*)&av[cur][kt * 8 + lq][lg];
            uint32_t b1 = *(const uint32_t*)&av[cur][kt * 8 + 4 + lq][lg];
            #pragma unroll
            for (int mi = 0; mi < 4; mi++)
                mma16816(acc[mi], Af[mi][kt], b0, b1, acc[mi]);
        }

        // ---- stage gates (cols 0..3 only) ----
        if (lq < 2) {
            #pragma unroll
            for (int mi = 0; mi < 4; mi++) {
                const int row = (wid * 4 + mi) * 16 + lg;
                *(float2*)&gates[row][lq * 2] =
                    make_float2(acc[mi][0], acc[mi][1]);
                *(float2*)&gates[row + 8][lq * 2] =
                    make_float2(acc[mi][2], acc[mi][3]);
            }
        }

        // ---- x(t+1) prefetch -> av[nxt].x (disjoint from readers of av[cur]) ----
        if (t + 1 < T_STEPS) {
            ((__half*)&av[nxt][xk >> 1][xn])[xk & 1] =
                g_xT[((size_t)(seq0 + xn) * T_STEPS + (t + 1)) * CH + xk];
        }
        __syncthreads();

        // ---- epilogue (warps 0..3): LSTM cells, h(t+1) -> av[nxt].h ----
        if (tid < HID) {
            const int u = tid;
            float4 gi = *(const float4*)gates[u];
            float4 gf = *(const float4*)gates[HID + u];
            float4 gg = *(const float4*)gates[2 * HID + u];
            float4 go = *(const float4*)gates[3 * HID + u];
            lstm_cell(gi.x, gf.x, gg.x, go.x, cs[0], hs[0]);
            lstm_cell(gi.y, gf.y, gg.y, go.y, cs[1], hs[1]);
            lstm_cell(gi.z, gf.z, gg.z, go.z, cs[2], hs[2]);
            lstm_cell(gi.w, gf.w, gg.w, go.w, cs[3], hs[3]);
            const int k2 = 32 + (u >> 1), hsel = u & 1;
            #pragma unroll
            for (int n = 0; n < TN; n++)
                ((__half*)&av[nxt][k2][n])[hsel] = __float2half_rn(hs[n]);
        }

        // ---- x-part for t+1 (kt 0..3, reads only av[nxt].x) — overlaps MUFU ----
        if (t + 1 < T_STEPS) {
            #pragma unroll
            for (int kt = 0; kt < 4; kt++) {
                uint32_t b0 = *(const uint32_t*)&av[nxt][kt * 8 + lq][lg];
                uint32_t b1 = *(const uint32_t*)&av[nxt][kt * 8 + 4 + lq][lg];
                #pragma unroll
                for (int mi = 0; mi < 4; mi++) {
                    if (kt == 0) {
                        const int rlo = (wid * 4 + mi) * 16 + lg;
                        float blo = sbias[rlo], bhi = sbias[rlo + 8];
                        float cb[4] = {blo, blo, bhi, bhi};
                        mma16816(acc[mi], Af[mi][0], b0, b1, cb);
                    } else {
                        mma16816(acc[mi], Af[mi][kt], b0, b1, acc[mi]);
                    }
                }
            }
        }
        __syncthreads();
    }

    // ---- final FC: out[seq][ch] = h . W_fc[ch] + b_fc[ch] ----
    float* hb = &gates[0][0];   // [TN][HID] staging, reuse gates (512 floats)
    if (tid < HID) {
        #pragma unroll
        for (int n = 0; n < TN; n++) hb[n * HID + tid] = hs[n];
    }
    __syncthreads();
    {
        const int n = tid >> 6, chn = tid & 63;
        const float4* wfc4 = (const float4*)(W_fc + chn * HID);
        const float4* hb4  = (const float4*)(hb + n * HID);
        float a = b_fc[chn];
        #pragma unroll
        for (int j4 = 0; j4 < HID / 4; j4++) {
            float4 wv = wfc4[j4];
            float4 hv = hb4[j4];
            a = fmaf(wv.x, hv.x, a);
            a = fmaf(wv.y, hv.y, a);
            a = fmaf(wv.z, hv.z, a);
            a = fmaf(wv.w, hv.w, a);
        }
        out[(size_t)(seq0 + n) * CH + chn] = a;
    }
}

// ---------------------------------------------------------------------------
extern "C" void kernel_launch(void* const* d_in, const int* in_sizes, int n_in,
                              void* d_out, int out_size) {
    const float* x    = (const float*)d_in[0];
    const float* W_ih = (const float*)d_in[1];
    const float* W_hh = (const float*)d_in[2];
    const float* b_ih = (const float*)d_in[3];
    const float* b_hh = (const float*)d_in[4];
    const float* W_fc = (const float*)d_in[5];
    const float* b_fc = (const float*)d_in[6];
    float* out = (float*)d_out;

    transpose_kernel<<<dim3(16, T_STEPS), 256>>>(x);
    lstm_kernel<<<NBLOCK, NTHREADS>>>(W_ih, W_hh, b_ih, b_hh, W_fc, b_fc, out);
}

// round 9
// speedup vs baseline: 4.1941x; 1.1508x over previous
#include <cuda_runtime.h>
#include <cuda_fp16.h>
#include <cstdint>

// Problem constants
#define T_STEPS   200
#define CH        64     // channels (LSTM input size)
#define HID       128    // hidden size
#define GATES     512    // 4*HID gate rows
#define KTOT      192    // CH + HID fused K
#define TN        4      // sequences per block
#define NSEQ      480    // 16*30
#define NBLOCK    120
#define NTHREADS  256
#define NKT       12     // K tiles of 16

// fp16 transposed x scratch: [seq][t][c]
__device__ __half g_xT[(size_t)NSEQ * T_STEPS * CH];

// ---------------------------------------------------------------------------
// Kernel 1: transpose x (B, C, T, P) -> g_xT (B*P, T, C) fp16
// ---------------------------------------------------------------------------
__global__ void transpose_kernel(const float* __restrict__ x) {
    const int b = blockIdx.x;   // 0..15
    const int t = blockIdx.y;   // 0..199
    __shared__ float s[30 * 65];

    const float* xb = x + (size_t)b * (CH * T_STEPS * 30) + (size_t)t * 30;
    for (int i = threadIdx.x; i < CH * 30; i += blockDim.x) {
        int c = i / 30, p = i - c * 30;
        s[p * 65 + c] = xb[(size_t)c * (T_STEPS * 30) + p];
    }
    __syncthreads();
    __half* outp = g_xT + ((size_t)b * 30) * (T_STEPS * CH) + (size_t)t * CH;
    for (int i = threadIdx.x; i < 30 * CH; i += blockDim.x) {
        int p = i >> 6, c = i & 63;
        outp[(size_t)p * (T_STEPS * CH) + c] = __float2half_rn(s[p * 65 + c]);
    }
}

// ---------------------------------------------------------------------------
// MUFU.TANH-based activations (1 MUFU each)
// ---------------------------------------------------------------------------
__device__ __forceinline__ float tanh_ap(float x) {
    float y;
    asm("tanh.approx.f32 %0, %1;" : "=f"(y) : "f"(x));
    return y;
}
__device__ __forceinline__ float sigm_ap(float x) {
    return fmaf(0.5f, tanh_ap(0.5f * x), 0.5f);
}
__device__ __forceinline__ void lstm_cell(float gi, float gf, float gg, float go,
                                          float& c, float& h) {
    float i_ = sigm_ap(gi);
    float f_ = sigm_ap(gf);
    float g_ = tanh_ap(gg);
    float o_ = sigm_ap(go);
    c = fmaf(f_, c, i_ * g_);
    h = o_ * tanh_ap(c);
}

// ---------------------------------------------------------------------------
// m16n8k16 f16 -> f32 mma (baseline PTX, runs on sm_103 fallback HMMA)
// ---------------------------------------------------------------------------
__device__ __forceinline__ void mma16816(float* d, const uint32_t* a,
                                         uint32_t b0, uint32_t b1,
                                         const float* c) {
    asm volatile(
        "mma.sync.aligned.m16n8k16.row.col.f32.f16.f16.f32 "
        "{%0,%1,%2,%3}, {%4,%5,%6,%7}, {%8,%9}, {%10,%11,%12,%13};"
        : "=f"(d[0]), "=f"(d[1]), "=f"(d[2]), "=f"(d[3])
        : "r"(a[0]), "r"(a[1]), "r"(a[2]), "r"(a[3]),
          "r"(b0), "r"(b1),
          "f"(c[0]), "f"(c[1]), "f"(c[2]), "f"(c[3]));
}

__device__ __forceinline__ float getW(const float* __restrict__ Wih,
                                      const float* __restrict__ Whh,
                                      int r, int k) {
    return (k < CH) ? Wih[r * CH + k] : Whh[r * HID + (k - CH)];
}
__device__ __forceinline__ uint32_t packw(const float* __restrict__ Wih,
                                          const float* __restrict__ Whh,
                                          int r, int k) {
    __half2 h = __floats2half2_rn(getW(Wih, Whh, r, k), getW(Wih, Whh, r, k + 1));
    return *(uint32_t*)&h;
}

// ---------------------------------------------------------------------------
// Kernel 2: persistent HMMA LSTM, in-register epilogue.
// 120 blocks x 256 threads, 4 seqs/block.
// Warp w owns gate rows {g*128 + w*16 .. +15} for all 4 gate types g ->
// all 4 gates of unit u live in one thread's fragments: epilogue is
// register-only (no gate staging, ONE __syncthreads per step).
// Weights = m16n8k16 A-fragments in registers (192 regs). B (x|h fp16)
// double-buffered in SMEM. x-part MMA of t+1 overlaps epilogue MUFUs.
// ---------------------------------------------------------------------------
__global__ void __launch_bounds__(NTHREADS, 1)
lstm_kernel(const float* __restrict__ W_ih, const float* __restrict__ W_hh,
            const float* __restrict__ b_ih, const float* __restrict__ b_hh,
            const float* __restrict__ W_fc, const float* __restrict__ b_fc,
            float* __restrict__ out) {
    // av[buf][k2][n]: half2 = {val[2k2], val[2k2+1]} for seq-col n
    __shared__ __align__(16) __half2 av[2][96][8];      // 6 KB
    __shared__ __align__(16) float hb[TN][HID];         // 2 KB (final FC stage)

    const int tid  = threadIdx.x;
    const int lane = tid & 31;
    const int wid  = tid >> 5;
    const int lg   = lane >> 2;   // fragment row group / n col
    const int lq   = lane & 3;    // fragment k pairs / n pairs
    const int seq0 = blockIdx.x * TN;

    // ---- preload weight A-fragments (mt = mi*8 + wid mapping) ----
    uint32_t Af[4][NKT][4];
    #pragma unroll
    for (int mi = 0; mi < 4; mi++) {           // mi = gate type i/f/g/o
        const int rlo = mi * HID + wid * 16 + lg;
        const int rhi = rlo + 8;
        #pragma unroll
        for (int kt = 0; kt < NKT; kt++) {
            const int kb = kt * 16 + lq * 2;
            Af[mi][kt][0] = packw(W_ih, W_hh, rlo, kb);
            Af[mi][kt][1] = packw(W_ih, W_hh, rhi, kb);
            Af[mi][kt][2] = packw(W_ih, W_hh, rlo, kb + 8);
            Af[mi][kt][3] = packw(W_ih, W_hh, rhi, kb + 8);
        }
    }
    // per-thread biases for its 8 gate rows
    float blo[4], bhi[4];
    #pragma unroll
    for (int mi = 0; mi < 4; mi++) {
        const int r = mi * HID + wid * 16 + lg;
        blo[mi] = b_ih[r] + b_hh[r];
        bhi[mi] = b_ih[r + 8] + b_hh[r + 8];
    }

    // ---- zero av (h(0)=0 and n=4..7 padding), then x(0) ----
    for (int i = tid; i < 2 * 96 * 8; i += NTHREADS) ((uint32_t*)av)[i] = 0u;
    __syncthreads();
    const int xn = tid >> 6, xk = tid & 63;
    const __half* xptr = g_xT + ((size_t)(seq0 + xn) * T_STEPS) * CH + xk;
    ((__half*)&av[0][xk >> 1][xn])[xk & 1] = xptr[0];
    __syncthreads();

    float acc[4][4];
    // ---- x-part for t=0 (kt 0..3), C = bias on kt 0 ----
    #pragma unroll
    for (int kt = 0; kt < 4; kt++) {
        uint32_t b0 = *(const uint32_t*)&av[0][kt * 8 + lq][lg];
        uint32_t b1 = *(const uint32_t*)&av[0][kt * 8 + 4 + lq][lg];
        #pragma unroll
        for (int mi = 0; mi < 4; mi++) {
            if (kt == 0) {
                float cb[4] = {blo[mi], blo[mi], bhi[mi], bhi[mi]};
                mma16816(acc[mi], Af[mi][0], b0, b1, cb);
            } else {
                mma16816(acc[mi], Af[mi][kt], b0, b1, acc[mi]);
            }
        }
    }

    // cell/hidden state for this thread's 4 cells:
    // j=0:(u0,s0) j=1:(u0,s1) j=2:(u1,s0) j=3:(u1,s1)
    // u0 = wid*16+lg, u1 = u0+8, s0 = 2*lq, s1 = 2*lq+1 (valid iff lq<2)
    const int u0 = wid * 16 + lg, u1 = u0 + 8;
    const int s0 = 2 * lq, s1 = s0 + 1;
    float cs[4] = {0.f, 0.f, 0.f, 0.f};
    float hs[4] = {0.f, 0.f, 0.f, 0.f};

    for (int t = 0; t < T_STEPS; t++) {
        const int cur = t & 1, nxt = cur ^ 1;

        // issue x(t+1) global load early (L2 latency hidden under h-MMA)
        __half xv = __float2half_rn(0.f);
        if (t + 1 < T_STEPS) xv = xptr[(size_t)(t + 1) * CH];

        // ---- h-part: kt 4..11 on av[cur] ----
        #pragma unroll
        for (int kt = 4; kt < NKT; kt++) {
            uint32_t b0 = *(const uint32_t*)&av[cur][kt * 8 + lq][lg];
            uint32_t b1 = *(const uint32_t*)&av[cur][kt * 8 + 4 + lq][lg];
            #pragma unroll
            for (int mi = 0; mi < 4; mi++)
                mma16816(acc[mi], Af[mi][kt], b0, b1, acc[mi]);
        }

        // x(t+1) -> av[nxt].x (no reader until after the sync)
        if (t + 1 < T_STEPS)
            ((__half*)&av[nxt][xk >> 1][xn])[xk & 1] = xv;

        // ---- in-register epilogue: 4 cells from acc fragments ----
        lstm_cell(acc[0][0], acc[1][0], acc[2][0], acc[3][0], cs[0], hs[0]);
        lstm_cell(acc[0][1], acc[1][1], acc[2][1], acc[3][1], cs[1], hs[1]);
        lstm_cell(acc[0][2], acc[1][2], acc[2][2], acc[3][2], cs[2], hs[2]);
        lstm_cell(acc[0][3], acc[1][3], acc[2][3], acc[3][3], cs[3], hs[3]);

        // h(t+1) -> av[nxt].h (k = 64+u), valid seq cols only
        if (lq < 2) {
            ((__half*)&av[nxt][32 + (u0 >> 1)][s0])[u0 & 1] = __float2half_rn(hs[0]);
            ((__half*)&av[nxt][32 + (u0 >> 1)][s1])[u0 & 1] = __float2half_rn(hs[1]);
            ((__half*)&av[nxt][32 + (u1 >> 1)][s0])[u1 & 1] = __float2half_rn(hs[2]);
            ((__half*)&av[nxt][32 + (u1 >> 1)][s1])[u1 & 1] = __float2half_rn(hs[3]);
        }
        __syncthreads();

        // ---- x-part for t+1 (kt 0..3, av[nxt]), C = bias; overlaps next phases
        if (t + 1 < T_STEPS) {
            #pragma unroll
            for (int kt = 0; kt < 4; kt++) {
                uint32_t b0 = *(const uint32_t*)&av[nxt][kt * 8 + lq][lg];
                uint32_t b1 = *(const uint32_t*)&av[nxt][kt * 8 + 4 + lq][lg];
                #pragma unroll
                for (int mi = 0; mi < 4; mi++) {
                    if (kt == 0) {
                        float cb[4] = {blo[mi], blo[mi], bhi[mi], bhi[mi]};
                        mma16816(acc[mi], Af[mi][0], b0, b1, cb);
                    } else {
                        mma16816(acc[mi], Af[mi][kt], b0, b1, acc[mi]);
                    }
                }
            }
        }
    }

    // ---- stage final h, then FC: out[seq][ch] = h . W_fc[ch] + b_fc[ch] ----
    if (lq < 2) {
        hb[s0][u0] = hs[0];
        hb[s1][u0] = hs[1];
        hb[s0][u1] = hs[2];
        hb[s1][u1] = hs[3];
    }
    __syncthreads();
    {
        const int n = tid >> 6, chn = tid & 63;
        const float4* wfc4 = (const float4*)(W_fc + chn * HID);
        const float4* hb4  = (const float4*)(&hb[n][0]);
        float a = b_fc[chn];
        #pragma unroll
        for (int j4 = 0; j4 < HID / 4; j4++) {
            float4 wv = wfc4[j4];
            float4 hv = hb4[j4];
            a = fmaf(wv.x, hv.x, a);
            a = fmaf(wv.y, hv.y, a);
            a = fmaf(wv.z, hv.z, a);
            a = fmaf(wv.w, hv.w, a);
        }
        out[(size_t)(seq0 + n) * CH + chn] = a;
    }
}

// ---------------------------------------------------------------------------
extern "C" void kernel_launch(void* const* d_in, const int* in_sizes, int n_in,
                              void* d_out, int out_size) {
    const float* x    = (const float*)d_in[0];
    const float* W_ih = (const float*)d_in[1];
    const float* W_hh = (const float*)d_in[2];
    const float* b_ih = (const float*)d_in[3];
    const float* b_hh = (const float*)d_in[4];
    const float* W_fc = (const float*)d_in[5];
    const float* b_fc = (const float*)d_in[6];
    float* out = (float*)d_out;

    transpose_kernel<<<dim3(16, T_STEPS), 256>>>(x);
    lstm_kernel<<<NBLOCK, NTHREADS>>>(W_ih, W_hh, b_ih, b_hh, W_fc, b_fc, out);
}

// round 12
// speedup vs baseline: 4.4201x; 1.0539x over previous
#include <cuda_runtime.h>
#include <cuda_fp16.h>
#include <cstdint>

// Problem constants
#define T_STEPS   200
#define CH        64     // channels (LSTM input size)
#define HID       128    // hidden size
#define GATES     512    // 4*HID gate rows
#define KTOT      192    // CH + HID fused K
#define TN        4      // sequences per block
#define NSEQ      480    // 16*30
#define NBLOCK    120
#define NTHREADS  256
#define NKT       12     // K tiles of 16

// fp16 transposed x scratch: [seq][t][c]
__device__ __half g_xT[(size_t)NSEQ * T_STEPS * CH];

// ---------------------------------------------------------------------------
// Kernel 1: transpose x (B, C, T, P) -> g_xT (B*P, T, C) fp16
// ---------------------------------------------------------------------------
__global__ void transpose_kernel(const float* __restrict__ x) {
    const int b = blockIdx.x;   // 0..15
    const int t = blockIdx.y;   // 0..199
    __shared__ float s[30 * 65];

    const float* xb = x + (size_t)b * (CH * T_STEPS * 30) + (size_t)t * 30;
    for (int i = threadIdx.x; i < CH * 30; i += blockDim.x) {
        int c = i / 30, p = i - c * 30;
        s[p * 65 + c] = xb[(size_t)c * (T_STEPS * 30) + p];
    }
    __syncthreads();
    __half* outp = g_xT + ((size_t)b * 30) * (T_STEPS * CH) + (size_t)t * CH;
    for (int i = threadIdx.x; i < 30 * CH; i += blockDim.x) {
        int p = i >> 6, c = i & 63;
        outp[(size_t)p * (T_STEPS * CH) + c] = __float2half_rn(s[p * 65 + c]);
    }
}

// ---------------------------------------------------------------------------
// MUFU.TANH-based activations (1 MUFU each)
// ---------------------------------------------------------------------------
__device__ __forceinline__ float tanh_ap(float x) {
    float y;
    asm("tanh.approx.f32 %0, %1;" : "=f"(y) : "f"(x));
    return y;
}
__device__ __forceinline__ float sigm_ap(float x) {
    return fmaf(0.5f, tanh_ap(0.5f * x), 0.5f);
}
__device__ __forceinline__ void lstm_cell(float gi, float gf, float gg, float go,
                                          float& c, float& h) {
    float i_ = sigm_ap(gi);
    float f_ = sigm_ap(gf);
    float g_ = tanh_ap(gg);
    float o_ = sigm_ap(go);
    c = fmaf(f_, c, i_ * g_);
    h = o_ * tanh_ap(c);
}

// ---------------------------------------------------------------------------
// m16n8k16 f16 -> f32 mma (baseline PTX, runs on sm_103 fallback HMMA)
// ---------------------------------------------------------------------------
__device__ __forceinline__ void mma16816(float* d, const uint32_t* a,
                                         uint32_t b0, uint32_t b1,
                                         const float* c) {
    asm volatile(
        "mma.sync.aligned.m16n8k16.row.col.f32.f16.f16.f32 "
        "{%0,%1,%2,%3}, {%4,%5,%6,%7}, {%8,%9}, {%10,%11,%12,%13};"
        : "=f"(d[0]), "=f"(d[1]), "=f"(d[2]), "=f"(d[3])
        : "r"(a[0]), "r"(a[1]), "r"(a[2]), "r"(a[3]),
          "r"(b0), "r"(b1),
          "f"(c[0]), "f"(c[1]), "f"(c[2]), "f"(c[3]));
}

__device__ __forceinline__ float getW(const float* __restrict__ Wih,
                                      const float* __restrict__ Whh,
                                      int r, int k) {
    return (k < CH) ? Wih[r * CH + k] : Whh[r * HID + (k - CH)];
}
__device__ __forceinline__ uint32_t packw(const float* __restrict__ Wih,
                                          const float* __restrict__ Whh,
                                          int r, int k) {
    __half2 h = __floats2half2_rn(getW(Wih, Whh, r, k), getW(Wih, Whh, r, k + 1));
    return *(uint32_t*)&h;
}

// ---------------------------------------------------------------------------
// Kernel 2: persistent HMMA LSTM.
// 120 blocks x 256 threads, 4 seqs/block. Warp w owns gate rows
// {g*128 + w*16 .. +15} for all 4 gate types g (mt = mi*8 + wid), so a
// unit's 4 gates land in one thread's accumulator fragments.
// Per step: ONE contiguous 12-kt (48 HMMA) region with bias as C on kt0,
// then a shuffle-balanced register epilogue (2 valid cells per thread:
// shfl.bfly xor=2 moves the u+8 cells' gates to the lq>=2 lanes),
// stores of x(t+1)/h(t+1) into the other av buffer, one __syncthreads.
// ---------------------------------------------------------------------------
__global__ void __launch_bounds__(NTHREADS, 1)
lstm_kernel(const float* __restrict__ W_ih, const float* __restrict__ W_hh,
            const float* __restrict__ b_ih, const float* __restrict__ b_hh,
            const float* __restrict__ W_fc, const float* __restrict__ b_fc,
            float* __restrict__ out) {
    // av[buf][k2][n]: half2 = {val[2k2], val[2k2+1]} for seq-col n
    __shared__ __align__(16) __half2 av[2][96][8];      // 6 KB
    __shared__ __align__(16) float hb[TN][HID];         // 2 KB (final FC stage)

    const int tid  = threadIdx.x;
    const int lane = tid & 31;
    const int wid  = tid >> 5;
    const int lg   = lane >> 2;   // fragment row group / n col
    const int lq   = lane & 3;    // fragment k pairs / n pairs
    const int seq0 = blockIdx.x * TN;

    // ---- preload weight A-fragments (mt = mi*8 + wid mapping) ----
    uint32_t Af[4][NKT][4];
    #pragma unroll
    for (int mi = 0; mi < 4; mi++) {           // mi = gate type i/f/g/o
        const int rlo = mi * HID + wid * 16 + lg;
        const int rhi = rlo + 8;
        #pragma unroll
        for (int kt = 0; kt < NKT; kt++) {
            const int kb = kt * 16 + lq * 2;
            Af[mi][kt][0] = packw(W_ih, W_hh, rlo, kb);
            Af[mi][kt][1] = packw(W_ih, W_hh, rhi, kb);
            Af[mi][kt][2] = packw(W_ih, W_hh, rlo, kb + 8);
            Af[mi][kt][3] = packw(W_ih, W_hh, rhi, kb + 8);
        }
    }
    // per-thread biases for its 8 gate rows
    float blo[4], bhi[4];
    #pragma unroll
    for (int mi = 0; mi < 4; mi++) {
        const int r = mi * HID + wid * 16 + lg;
        blo[mi] = b_ih[r] + b_hh[r];
        bhi[mi] = b_ih[r + 8] + b_hh[r + 8];
    }

    // ---- zero av (h(0)=0 and n=4..7 padding), then x(0) ----
    for (int i = tid; i < 2 * 96 * 8; i += NTHREADS) ((uint32_t*)av)[i] = 0u;
    __syncthreads();
    const int xn = tid >> 6, xk = tid & 63;
    const __half* xptr = g_xT + ((size_t)(seq0 + xn) * T_STEPS) * CH + xk;
    ((__half*)&av[0][xk >> 1][xn])[xk & 1] = xptr[0];
    __syncthreads();

    // this thread's 2 cells after shuffle balancing:
    //   hi = (lq >= 2); u = wid*16 + lg + (hi ? 8 : 0)
    //   s0 = 2*(lq&1), s1 = s0+1
    const bool hi = (lq >= 2);
    const int u  = wid * 16 + lg + (hi ? 8 : 0);
    const int s0 = 2 * (lq & 1), s1 = s0 + 1;

    float acc[4][4];
    float cs[2] = {0.f, 0.f};
    float hs[2] = {0.f, 0.f};

    for (int t = 0; t < T_STEPS; t++) {
        const int cur = t & 1, nxt = cur ^ 1;

        // issue x(t+1) global load early (latency hidden under the MMA block)
        __half xv = __float2half_rn(0.f);
        if (t + 1 < T_STEPS) xv = xptr[(size_t)(t + 1) * CH];

        // ---- one contiguous GEMM: kt 0..11, bias as C on kt0 ----
        #pragma unroll
        for (int kt = 0; kt < NKT; kt++) {
            uint32_t b0 = *(const uint32_t*)&av[cur][kt * 8 + lq][lg];
            uint32_t b1 = *(const uint32_t*)&av[cur][kt * 8 + 4 + lq][lg];
            #pragma unroll
            for (int mi = 0; mi < 4; mi++) {
                if (kt == 0) {
                    float cb[4] = {blo[mi], blo[mi], bhi[mi], bhi[mi]};
                    mma16816(acc[mi], Af[mi][0], b0, b1, cb);
                } else {
                    mma16816(acc[mi], Af[mi][kt], b0, b1, acc[mi]);
                }
            }
        }

        // ---- shuffle-balance: send u+8 cells' gates to lq>=2 lanes ----
        float g0[4], g1[4];
        #pragma unroll
        for (int mi = 0; mi < 4; mi++) {
            float r0 = __shfl_xor_sync(0xffffffffu, acc[mi][2], 2);
            float r1 = __shfl_xor_sync(0xffffffffu, acc[mi][3], 2);
            g0[mi] = hi ? r0 : acc[mi][0];
            g1[mi] = hi ? r1 : acc[mi][1];
        }

        // ---- 2 cells per thread, all valid ----
        lstm_cell(g0[0], g0[1], g0[2], g0[3], cs[0], hs[0]);
        lstm_cell(g1[0], g1[1], g1[2], g1[3], cs[1], hs[1]);

        // ---- stores into av[nxt]: x(t+1) and h(t+1) ----
        if (t + 1 < T_STEPS)
            ((__half*)&av[nxt][xk >> 1][xn])[xk & 1] = xv;
        ((__half*)&av[nxt][32 + (u >> 1)][s0])[u & 1] = __float2half_rn(hs[0]);
        ((__half*)&av[nxt][32 + (u >> 1)][s1])[u & 1] = __float2half_rn(hs[1]);
        __syncthreads();
    }

    // ---- stage final h, then FC: out[seq][ch] = h . W_fc[ch] + b_fc[ch] ----
    hb[s0][u] = hs[0];
    hb[s1][u] = hs[1];
    __syncthreads();
    {
        const int n = tid >> 6, chn = tid & 63;
        const float4* wfc4 = (const float4*)(W_fc + chn * HID);
        const float4* hb4  = (const float4*)(&hb[n][0]);
        float a = b_fc[chn];
        #pragma unroll
        for (int j4 = 0; j4 < HID / 4; j4++) {
            float4 wv = wfc4[j4];
            float4 hv = hb4[j4];
            a = fmaf(wv.x, hv.x, a);
            a = fmaf(wv.y, hv.y, a);
            a = fmaf(wv.z, hv.z, a);
            a = fmaf(wv.w, hv.w, a);
        }
        out[(size_t)(seq0 + n) * CH + chn] = a;
    }
}

// ---------------------------------------------------------------------------
extern "C" void kernel_launch(void* const* d_in, const int* in_sizes, int n_in,
                              void* d_out, int out_size) {
    const float* x    = (const float*)d_in[0];
    const float* W_ih = (const float*)d_in[1];
    const float* W_hh = (const float*)d_in[2];
    const float* b_ih = (const float*)d_in[3];
    const float* b_hh = (const float*)d_in[4];
    const float* W_fc = (const float*)d_in[5];
    const float* b_fc = (const float*)d_in[6];
    float* out = (float*)d_out;

    transpose_kernel<<<dim3(16, T_STEPS), 256>>>(x);
    lstm_kernel<<<NBLOCK, NTHREADS>>>(W_ih, W_hh, b_ih, b_hh, W_fc, b_fc, out);
}